// round 3
// baseline (speedup 1.0000x reference)
#include <cuda_runtime.h>

// ============================================================================
// GATv2 x2 + BN + skip + linear head, fused pipeline.
// edge_index arrives as INT32 (harness dtype set is {float32,int32,bf16};
// jnp.int64 without x64 is silently int32).
//
// Pipeline:
//   1. prep:      pack [Wl1|Wr1|Ws] -> g_W1 (160x576), [Wl2|Wr2] -> g_W2
//                 (256x128), fold bias+BN into per-channel scale/shift.
//   2. CSR build: deg count (self-loop incl) -> scan -> self-loop -> scatter.
//   3. GEMM1:     g_xlr1[N,576] = x @ g_W1 + g_b1c   (xl1 | xr1 | x_skip)
//   4. conv1 agg: warp/dst online-softmax, fused bias+BN1+relu -> g_h[N,256]
//   5. GEMM2:     g_xlr2[N,128] = g_h @ g_W2 + g_b2c (xl2 | xr2)
//   6. conv2 agg: warp/dst online-softmax, fused BN2+relu+skip+head -> d_out
// ============================================================================

#define NEG_SLOPE 0.2f

static constexpr int NMAX  = 50000;
static constexpr int EMAX  = 800000;
static constexpr int EPMAX = EMAX + NMAX;

// ---- scratch ---------------------------------------------------------------
__device__ float g_xlr1[(size_t)NMAX * 576];   // xl1[0:256) | xr1[256:512) | skip[512:576)
__device__ float g_h   [(size_t)NMAX * 256];
__device__ float g_xlr2[(size_t)NMAX * 128];   // xl2[0:64) | xr2[64:128)
__device__ int   g_deg [NMAX];
__device__ int   g_off [NMAX + 1];
__device__ int   g_cur [NMAX];
__device__ int   g_esrc[EPMAX];
__device__ float g_W1  [160 * 576];
__device__ float g_b1c [576];
__device__ float g_W2  [256 * 128];
__device__ float g_b2c [128];
__device__ float g_c1a [256];
__device__ float g_c1b [256];
__device__ float g_c2a [64];
__device__ float g_c2b [64];

// ---- 1. prep ---------------------------------------------------------------
__global__ void prep_kernel(
    const float* __restrict__ Wl1, const float* __restrict__ bl1,
    const float* __restrict__ Wr1, const float* __restrict__ br1,
    const float* __restrict__ Ws,  const float* __restrict__ bs,
    const float* __restrict__ Wl2, const float* __restrict__ bl2,
    const float* __restrict__ Wr2, const float* __restrict__ br2,
    const float* __restrict__ bias1, const float* __restrict__ g1,
    const float* __restrict__ b1,  const float* __restrict__ m1,
    const float* __restrict__ v1,
    const float* __restrict__ bias2, const float* __restrict__ g2,
    const float* __restrict__ b2,  const float* __restrict__ m2,
    const float* __restrict__ v2)
{
    int i = blockIdx.x * blockDim.x + threadIdx.x;
    if (i < 92160) {
        int k = i / 576, m = i % 576;
        float v;
        if (m < 256)      v = Wl1[k * 256 + m];
        else if (m < 512) v = Wr1[k * 256 + (m - 256)];
        else              v = Ws [k * 64  + (m - 512)];
        g_W1[i] = v;
    } else if (i < 92736) {
        int m = i - 92160;
        g_b1c[m] = (m < 256) ? bl1[m] : ((m < 512) ? br1[m - 256] : bs[m - 512]);
    } else if (i < 125504) {
        int j = i - 92736;
        int k = j / 128, m = j % 128;
        g_W2[j] = (m < 64) ? Wl2[k * 64 + m] : Wr2[k * 64 + (m - 64)];
    } else if (i < 125632) {
        int m = i - 125504;
        g_b2c[m] = (m < 64) ? bl2[m] : br2[m - 64];
    } else if (i < 125888) {
        int j = i - 125632;
        float sc = g1[j] * rsqrtf(v1[j] + 1e-5f);
        g_c1a[j] = sc;
        g_c1b[j] = (bias1[j] - m1[j]) * sc + b1[j];
    } else if (i < 125952) {
        int j = i - 125888;
        float sc = g2[j] * rsqrtf(v2[j] + 1e-5f);
        g_c2a[j] = sc;
        g_c2b[j] = (bias2[j] - m2[j]) * sc + b2[j];
    }
}

// ---- 2. CSR build ----------------------------------------------------------
__global__ void init_deg_kernel(int n) {
    int i = blockIdx.x * blockDim.x + threadIdx.x;
    if (i < n) g_deg[i] = 1;  // self-loop
}

__global__ void count_kernel(const int* __restrict__ ei, int e, int n) {
    int i = blockIdx.x * blockDim.x + threadIdx.x;
    if (i < e) {
        int d = ei[e + i];
        if (d >= 0 && d < n) atomicAdd(&g_deg[d], 1);
    }
}

__global__ void scan_kernel(int n) {
    __shared__ int sh[1024];
    __shared__ int carry;
    if (threadIdx.x == 0) { carry = 0; g_off[0] = 0; }
    __syncthreads();
    for (int base = 0; base < n; base += 1024) {
        int i = base + threadIdx.x;
        int v = (i < n) ? g_deg[i] : 0;
        sh[threadIdx.x] = v;
        __syncthreads();
        for (int off = 1; off < 1024; off <<= 1) {
            int t = (threadIdx.x >= off) ? sh[threadIdx.x - off] : 0;
            __syncthreads();
            sh[threadIdx.x] += t;
            __syncthreads();
        }
        int c = carry;
        if (i < n) g_off[i + 1] = c + sh[threadIdx.x];
        __syncthreads();
        if (threadIdx.x == 0) carry = c + sh[1023];
        __syncthreads();
    }
}

__global__ void selfloop_kernel(int n) {
    int i = blockIdx.x * blockDim.x + threadIdx.x;
    if (i < n) {
        int o = g_off[i];
        g_esrc[o] = i;
        g_cur[i] = o + 1;
    }
}

__global__ void scatter_kernel(const int* __restrict__ ei, int e, int n) {
    int i = blockIdx.x * blockDim.x + threadIdx.x;
    if (i < e) {
        int s = ei[i];
        int d = ei[e + i];
        if (s >= 0 && s < n && d >= 0 && d < n) {
            int pos = atomicAdd(&g_cur[d], 1);
            g_esrc[pos] = s;
        }
    }
}

// ---- 3/5. fp32 tiled GEMM (templated on operand set; globals direct) -------
// MODE 0: g_xlr1 = Aext(x)[N,160] @ g_W1[160,576] + g_b1c
// MODE 1: g_xlr2 = g_h[N,256]     @ g_W2[256,128] + g_b2c
template <int MODE>
__global__ __launch_bounds__(256) void gemm_bias_kernel(
    const float* __restrict__ Aext, int N)
{
    constexpr int K = (MODE == 0) ? 160 : 256;
    constexpr int M = (MODE == 0) ? 576 : 128;
    const float* __restrict__ A    = (MODE == 0) ? Aext : g_h;
    const float* __restrict__ B    = (MODE == 0) ? g_W1 : g_W2;
    const float* __restrict__ bias = (MODE == 0) ? g_b1c : g_b2c;
    float* __restrict__ C          = (MODE == 0) ? g_xlr1 : g_xlr2;

    __shared__ float As[16][64];
    __shared__ float Bs[16][64];
    int tid = threadIdx.x;
    int tx = tid & 15, ty = tid >> 4;
    int rowBase = blockIdx.y * 64, colBase = blockIdx.x * 64;

    float acc[4][4];
#pragma unroll
    for (int i = 0; i < 4; i++)
#pragma unroll
        for (int j = 0; j < 4; j++) acc[i][j] = 0.f;

    for (int k0 = 0; k0 < K; k0 += 16) {
        {   // A tile: 64 rows x 16 k, one float4 per thread
            int r = tid >> 2, kq = tid & 3;
            int row = rowBase + r;
            float4 v = make_float4(0.f, 0.f, 0.f, 0.f);
            if (row < N)
                v = *(const float4*)(A + (size_t)row * K + k0 + kq * 4);
            As[kq * 4 + 0][r] = v.x;
            As[kq * 4 + 1][r] = v.y;
            As[kq * 4 + 2][r] = v.z;
            As[kq * 4 + 3][r] = v.w;
        }
        {   // B tile: 16 k x 64 cols, one float4 per thread
            int kk = tid >> 4, cq = tid & 15;
            float4 v = *(const float4*)(B + (size_t)(k0 + kk) * M + colBase + cq * 4);
            *(float4*)&Bs[kk][cq * 4] = v;
        }
        __syncthreads();
#pragma unroll
        for (int kk = 0; kk < 16; kk++) {
            float4 a = *(const float4*)&As[kk][ty * 4];
            float4 b = *(const float4*)&Bs[kk][tx * 4];
            acc[0][0] += a.x * b.x; acc[0][1] += a.x * b.y; acc[0][2] += a.x * b.z; acc[0][3] += a.x * b.w;
            acc[1][0] += a.y * b.x; acc[1][1] += a.y * b.y; acc[1][2] += a.y * b.z; acc[1][3] += a.y * b.w;
            acc[2][0] += a.z * b.x; acc[2][1] += a.z * b.y; acc[2][2] += a.z * b.z; acc[2][3] += a.z * b.w;
            acc[3][0] += a.w * b.x; acc[3][1] += a.w * b.y; acc[3][2] += a.w * b.z; acc[3][3] += a.w * b.w;
        }
        __syncthreads();
    }

    float4 bb = *(const float4*)(bias + colBase + tx * 4);
#pragma unroll
    for (int i = 0; i < 4; i++) {
        int row = rowBase + ty * 4 + i;
        if (row < N) {
            float4 o;
            o.x = acc[i][0] + bb.x;
            o.y = acc[i][1] + bb.y;
            o.z = acc[i][2] + bb.z;
            o.w = acc[i][3] + bb.w;
            *(float4*)(C + (size_t)row * M + colBase + tx * 4) = o;
        }
    }
}

// ---- 4. conv1 aggregation: one warp per dst --------------------------------
__device__ __forceinline__ float lrelu(float t) {
    return fmaxf(t, 0.f) + NEG_SLOPE * fminf(t, 0.f);
}

__global__ __launch_bounds__(256) void conv1_agg_kernel(
    const float* __restrict__ att1, int n)
{
    int gw = (blockIdx.x * blockDim.x + threadIdx.x) >> 5;
    int lane = threadIdx.x & 31;
    if (gw >= n) return;

    const float* xr_p = g_xlr1 + (size_t)gw * 576 + 256 + lane * 8;
    float4 xr0 = *(const float4*)xr_p;
    float4 xr1 = *(const float4*)(xr_p + 4);
    float4 at0 = *(const float4*)(att1 + lane * 8);
    float4 at1 = *(const float4*)(att1 + lane * 8 + 4);

    float m = -3.0e38f, den = 0.f;
    float acc[8];
#pragma unroll
    for (int j = 0; j < 8; j++) acc[j] = 0.f;

    int e0 = g_off[gw], e1 = g_off[gw + 1];
    for (int e = e0; e < e1; ++e) {
        int s = g_esrc[e];
        const float* xl_p = g_xlr1 + (size_t)s * 576 + lane * 8;
        float4 x0 = *(const float4*)xl_p;
        float4 x1 = *(const float4*)(xl_p + 4);

        float p;
        p  = at0.x * lrelu(x0.x + xr0.x);
        p += at0.y * lrelu(x0.y + xr0.y);
        p += at0.z * lrelu(x0.z + xr0.z);
        p += at0.w * lrelu(x0.w + xr0.w);
        p += at1.x * lrelu(x1.x + xr1.x);
        p += at1.y * lrelu(x1.y + xr1.y);
        p += at1.z * lrelu(x1.z + xr1.z);
        p += at1.w * lrelu(x1.w + xr1.w);
        p += __shfl_xor_sync(0xffffffffu, p, 1);
        p += __shfl_xor_sync(0xffffffffu, p, 2);
        p += __shfl_xor_sync(0xffffffffu, p, 4);

        float nm = fmaxf(m, p);
        float cf = __expf(m - nm);
        float w  = __expf(p - nm);
        den = den * cf + w;
        acc[0] = acc[0] * cf + w * x0.x;
        acc[1] = acc[1] * cf + w * x0.y;
        acc[2] = acc[2] * cf + w * x0.z;
        acc[3] = acc[3] * cf + w * x0.w;
        acc[4] = acc[4] * cf + w * x1.x;
        acc[5] = acc[5] * cf + w * x1.y;
        acc[6] = acc[6] * cf + w * x1.z;
        acc[7] = acc[7] * cf + w * x1.w;
        m = nm;
    }

    float inv = 1.f / den;
    int c = lane * 8;
    float4 o0, o1;
    o0.x = fmaxf(acc[0] * inv * g_c1a[c + 0] + g_c1b[c + 0], 0.f);
    o0.y = fmaxf(acc[1] * inv * g_c1a[c + 1] + g_c1b[c + 1], 0.f);
    o0.z = fmaxf(acc[2] * inv * g_c1a[c + 2] + g_c1b[c + 2], 0.f);
    o0.w = fmaxf(acc[3] * inv * g_c1a[c + 3] + g_c1b[c + 3], 0.f);
    o1.x = fmaxf(acc[4] * inv * g_c1a[c + 4] + g_c1b[c + 4], 0.f);
    o1.y = fmaxf(acc[5] * inv * g_c1a[c + 5] + g_c1b[c + 5], 0.f);
    o1.z = fmaxf(acc[6] * inv * g_c1a[c + 6] + g_c1b[c + 6], 0.f);
    o1.w = fmaxf(acc[7] * inv * g_c1a[c + 7] + g_c1b[c + 7], 0.f);
    *(float4*)(g_h + (size_t)gw * 256 + c)     = o0;
    *(float4*)(g_h + (size_t)gw * 256 + c + 4) = o1;
}

// ---- 6. conv2 aggregation + BN2 + relu + skip + head -----------------------
__global__ __launch_bounds__(256) void conv2_agg_kernel(
    const float* __restrict__ att2, const float* __restrict__ Wo,
    const float* __restrict__ bo, float* __restrict__ out, int n)
{
    int gw = (blockIdx.x * blockDim.x + threadIdx.x) >> 5;
    int lane = threadIdx.x & 31;
    if (gw >= n) return;

    float2 xr = *(const float2*)(g_xlr2 + (size_t)gw * 128 + 64 + lane * 2);
    float2 at = *(const float2*)(att2 + lane * 2);

    float m = -3.0e38f, den = 0.f, a0 = 0.f, a1 = 0.f;

    int e0 = g_off[gw], e1 = g_off[gw + 1];
    for (int e = e0; e < e1; ++e) {
        int s = g_esrc[e];
        float2 x = *(const float2*)(g_xlr2 + (size_t)s * 128 + lane * 2);
        float p = at.x * lrelu(x.x + xr.x) + at.y * lrelu(x.y + xr.y);
        p += __shfl_xor_sync(0xffffffffu, p, 1);
        p += __shfl_xor_sync(0xffffffffu, p, 2);
        p += __shfl_xor_sync(0xffffffffu, p, 4);
        p += __shfl_xor_sync(0xffffffffu, p, 8);
        p += __shfl_xor_sync(0xffffffffu, p, 16);

        float nm = fmaxf(m, p);
        float cf = __expf(m - nm);
        float w  = __expf(p - nm);
        den = den * cf + w;
        a0 = a0 * cf + w * x.x;
        a1 = a1 * cf + w * x.y;
        m = nm;
    }

    float inv = 1.f / den;
    int c = lane * 2;
    float2 sk = *(const float2*)(g_xlr1 + (size_t)gw * 576 + 512 + c);
    float h0 = fmaxf(a0 * inv * g_c2a[c + 0] + g_c2b[c + 0], 0.f) + sk.x;
    float h1 = fmaxf(a1 * inv * g_c2a[c + 1] + g_c2b[c + 1], 0.f) + sk.y;

    float r = h0 * Wo[c] + h1 * Wo[c + 1];
    r += __shfl_xor_sync(0xffffffffu, r, 1);
    r += __shfl_xor_sync(0xffffffffu, r, 2);
    r += __shfl_xor_sync(0xffffffffu, r, 4);
    r += __shfl_xor_sync(0xffffffffu, r, 8);
    r += __shfl_xor_sync(0xffffffffu, r, 16);
    if (lane == 0) out[gw] = r + bo[0];
}

// ---- host ------------------------------------------------------------------
extern "C" void kernel_launch(void* const* d_in, const int* in_sizes, int n_in,
                              void* d_out, int out_size)
{
    const float* x     = (const float*)d_in[0];
    const int*   ei    = (const int*)d_in[1];          // int32 (see header note)
    const float* Wl1   = (const float*)d_in[2];
    const float* bl1   = (const float*)d_in[3];
    const float* Wr1   = (const float*)d_in[4];
    const float* br1   = (const float*)d_in[5];
    const float* att1  = (const float*)d_in[6];
    const float* bias1 = (const float*)d_in[7];
    const float* g1    = (const float*)d_in[8];
    const float* b1    = (const float*)d_in[9];
    const float* m1    = (const float*)d_in[10];
    const float* v1    = (const float*)d_in[11];
    const float* Wl2   = (const float*)d_in[12];
    const float* bl2   = (const float*)d_in[13];
    const float* Wr2   = (const float*)d_in[14];
    const float* br2   = (const float*)d_in[15];
    const float* att2  = (const float*)d_in[16];
    const float* bias2 = (const float*)d_in[17];
    const float* g2    = (const float*)d_in[18];
    const float* b2    = (const float*)d_in[19];
    const float* m2    = (const float*)d_in[20];
    const float* v2    = (const float*)d_in[21];
    const float* Ws    = (const float*)d_in[22];
    const float* bs    = (const float*)d_in[23];
    const float* Wo    = (const float*)d_in[24];
    const float* bo    = (const float*)d_in[25];

    int n = in_sizes[0] / 160;
    int e = in_sizes[1] / 2;

    // 1. prep
    prep_kernel<<<(125952 + 255) / 256, 256>>>(
        Wl1, bl1, Wr1, br1, Ws, bs, Wl2, bl2, Wr2, br2,
        bias1, g1, b1, m1, v1, bias2, g2, b2, m2, v2);

    // 2. CSR build
    init_deg_kernel<<<(n + 255) / 256, 256>>>(n);
    count_kernel<<<(e + 255) / 256, 256>>>(ei, e, n);
    scan_kernel<<<1, 1024>>>(n);
    selfloop_kernel<<<(n + 255) / 256, 256>>>(n);
    scatter_kernel<<<(e + 255) / 256, 256>>>(ei, e, n);

    // 3. GEMM1
    {
        dim3 grid(576 / 64, (n + 63) / 64);
        gemm_bias_kernel<0><<<grid, 256>>>(x, n);
    }

    // 4. conv1 aggregation
    conv1_agg_kernel<<<(n + 7) / 8, 256>>>(att1, n);

    // 5. GEMM2
    {
        dim3 grid(128 / 64, (n + 63) / 64);
        gemm_bias_kernel<1><<<grid, 256>>>(nullptr, n);
    }

    // 6. conv2 aggregation
    conv2_agg_kernel<<<(n + 7) / 8, 256>>>(att2, Wo, bo, (float*)d_out, n);
}